// round 10
// baseline (speedup 1.0000x reference)
#include <cuda_runtime.h>
#include <cuda_fp16.h>

#define NN_MAX 100000
#define NE_MAX 1600000
#define D 128
#define MAXG 4096
#define WS_STRIDE 136

// ---------------- scratch (static device globals; no allocs) ----------------
// NOTE: g_degi starts zero-initialized (module load) and is re-zeroed by
// k_scan1 on every launch, so no memset node is needed.
__device__ __align__(16) __half g_h[NN_MAX * D];
__device__ __align__(16) __half g_agg[NN_MAX * D];
__device__ __align__(16) __half g_Wh[3 * D * D];
__device__ int   g_degi[NN_MAX];
__device__ int   g_off[NN_MAX + 1];
__device__ int   g_cur[NN_MAX];
__device__ int   g_esrc[NE_MAX];
__device__ float g_hg[MAXG * D];
__device__ float g_cnt[MAXG];
__device__ int   g_part[1024];

// ---------------- degree count (CSR branch) ----------------
__global__ void k_deg(const int* __restrict__ dst, int ne) {
    int i = blockIdx.x * blockDim.x + threadIdx.x;
    if (i < ne) atomicAdd(&g_degi[dst[i]], 1);
}

// ------- feat->fp16 (cols 1..127) + W conv + hg/cnt zero (side branch) ------
__global__ void k_feat(const float* __restrict__ feat,
                       const float* __restrict__ W0, const float* __restrict__ W1,
                       const float* __restrict__ W2, int n, int ng) {
    int idx = blockIdx.x * blockDim.x + threadIdx.x;
    if (idx < D * D) {
        g_Wh[idx] = __float2half(W0[idx]);
        g_Wh[D * D + idx] = __float2half(W1[idx]);
        g_Wh[2 * D * D + idx] = __float2half(W2[idx]);
    }
    if (idx < ng * D) g_hg[idx] = 0.f;
    if (idx < ng) g_cnt[idx] = 0.f;
    if (idx < n * D) {
        int d = idx & (D - 1);
        if (d != 0) {
            int node = idx >> 7;
            g_h[idx] = __float2half(feat[node * (D - 1) + d - 1]);
        }
    }
}

// -------- scan pass 1 (+ writes h[:,0]=deg, self-clears g_degi) -------------
__global__ void k_scan1(int n) {
    __shared__ int sh[1024];
    int t = threadIdx.x, gid = blockIdx.x * 1024 + t;
    int v = (gid < n) ? g_degi[gid] : 0;
    if (gid < n) {
        g_h[(size_t)gid * D] = __float2half((float)v);
        g_degi[gid] = 0;  // re-zero for the next graph replay
    }
    sh[t] = v;
    __syncthreads();
    for (int s = 1; s < 1024; s <<= 1) {
        int u = (t >= s) ? sh[t - s] : 0;
        __syncthreads();
        sh[t] += u;
        __syncthreads();
    }
    if (gid < n) g_off[gid] = sh[t] - v;
    if (t == 1023) g_part[blockIdx.x] = sh[1023];
}

// ---------------- scan pass 2: partial-scan per block + apply; primes g_cur -
__global__ void k_scan2b(int n, int ne, int nb) {
    __shared__ int sh[1024];
    int t = threadIdx.x;
    int v = (t < nb) ? g_part[t] : 0;
    sh[t] = v;
    __syncthreads();
    for (int s = 1; s < 1024; s <<= 1) {
        int u = (t >= s) ? sh[t - s] : 0;
        __syncthreads();
        sh[t] += u;
        __syncthreads();
    }
    int prefix = sh[blockIdx.x] - ((blockIdx.x < nb) ? g_part[blockIdx.x] : 0);
    int gid = blockIdx.x * 1024 + t;
    if (gid < n) {
        int o = g_off[gid] + prefix;
        g_off[gid] = o;
        g_cur[gid] = o;
    }
    if (gid == 0) g_off[n] = ne;
}

// ---------------- CSR fill: 8 edges/thread, batched atomics (MLP=8) ---------
__global__ void k_fill(const int* __restrict__ src, const int* __restrict__ dst,
                       int ne, int nth) {
    int t = blockIdx.x * blockDim.x + threadIdx.x;
    int i[8], d[8], s[8], p[8];
#pragma unroll
    for (int j = 0; j < 8; j++) {
        i[j] = t + j * nth;
        d[j] = 0; s[j] = 0;
        if (i[j] < ne) { d[j] = dst[i[j]]; s[j] = src[i[j]]; }
    }
#pragma unroll
    for (int j = 0; j < 8; j++)
        if (i[j] < ne) p[j] = atomicAdd(&g_cur[d[j]], 1);
#pragma unroll
    for (int j = 0; j < 8; j++)
        if (i[j] < ne) g_esrc[p[j]] = s[j];
}

// ------- aggregation: warp/node, uint4 gather, predicated batched tail ------
__global__ void k_agg(const __half* __restrict__ hin, __half* __restrict__ aout, int n) {
    int warp = (blockIdx.x * blockDim.x + threadIdx.x) >> 5;
    int lane = threadIdx.x & 31;
    if (warp >= n) return;
    int hf = lane >> 4;     // 0 or 1 (which edge of the pair)
    int l16 = lane & 15;    // position within the row (8 halves each)
    int e0 = g_off[warp], e1 = g_off[warp + 1];
    const uint4* H = (const uint4*)hin;
    float acc[8];
#pragma unroll
    for (int i = 0; i < 8; i++) acc[i] = 0.f;

    int e = e0;
    for (; e + 7 < e1; e += 8) {
        int s[4];
#pragma unroll
        for (int j = 0; j < 4; j++) s[j] = g_esrc[e + 2 * j + hf];
        uint4 v[4];
#pragma unroll
        for (int j = 0; j < 4; j++) v[j] = H[(size_t)s[j] * 16 + l16];
#pragma unroll
        for (int j = 0; j < 4; j++) {
            float2 f;
            f = __half22float2(*(__half2*)&v[j].x); acc[0] += f.x; acc[1] += f.y;
            f = __half22float2(*(__half2*)&v[j].y); acc[2] += f.x; acc[3] += f.y;
            f = __half22float2(*(__half2*)&v[j].z); acc[4] += f.x; acc[5] += f.y;
            f = __half22float2(*(__half2*)&v[j].w); acc[6] += f.x; acc[7] += f.y;
        }
    }
    if (e < e1) {
        uint4 v[4];
#pragma unroll
        for (int j = 0; j < 4; j++) {
            int idx = e + 2 * j + hf;
            v[j] = make_uint4(0u, 0u, 0u, 0u);
            if (idx < e1) v[j] = H[(size_t)g_esrc[idx] * 16 + l16];
        }
#pragma unroll
        for (int j = 0; j < 4; j++) {
            float2 f;
            f = __half22float2(*(__half2*)&v[j].x); acc[0] += f.x; acc[1] += f.y;
            f = __half22float2(*(__half2*)&v[j].y); acc[2] += f.x; acc[3] += f.y;
            f = __half22float2(*(__half2*)&v[j].z); acc[4] += f.x; acc[5] += f.y;
            f = __half22float2(*(__half2*)&v[j].w); acc[6] += f.x; acc[7] += f.y;
        }
    }

#pragma unroll
    for (int i = 0; i < 8; i++) acc[i] += __shfl_xor_sync(0xffffffffu, acc[i], 16);

    int cnt = e1 - e0;
    if (lane < 16) {
        uint4 o;
        if (cnt > 0) {
            float inv = 1.0f / (float)cnt;
            __half2 h0 = __floats2half2_rn(acc[0] * inv, acc[1] * inv);
            __half2 h1 = __floats2half2_rn(acc[2] * inv, acc[3] * inv);
            __half2 h2 = __floats2half2_rn(acc[4] * inv, acc[5] * inv);
            __half2 h3 = __floats2half2_rn(acc[6] * inv, acc[7] * inv);
            o.x = *(unsigned*)&h0;
            o.y = *(unsigned*)&h1;
            o.z = *(unsigned*)&h2;
            o.w = *(unsigned*)&h3;
        } else {
            o = H[(size_t)warp * 16 + l16];  // zero in-degree keeps old h
        }
        ((uint4*)aout)[(size_t)warp * 16 + l16] = o;
    }
}

// ---------------- tensor-core GEMM (fp16 m16n8k16): out = relu(A @ W^T + b) --
__global__ __launch_bounds__(256, 2) void k_gemm_hc(const __half* __restrict__ A,
                                                    const __half* __restrict__ Wh,
                                                    const float* __restrict__ bias,
                                                    __half* __restrict__ out,
                                                    int n) {
    extern __shared__ __half ws[];  // [128][WS_STRIDE]
    int tid = threadIdx.x;

    const uint4* Wv = (const uint4*)Wh;
    for (int i = tid; i < 2048; i += 256) {
        int nrow = i >> 4;
        int kk = (i & 15) * 8;
        *(uint4*)&ws[nrow * WS_STRIDE + kk] = Wv[i];
    }
    __syncthreads();

    int warp = tid >> 5, lane = tid & 31;
    int g = lane >> 2;
    int t4 = lane & 3;
    int row0 = blockIdx.x * 128 + warp * 16;
    int r1 = row0 + g;
    int r2 = row0 + g + 8;
    const __half* a1p = A + (size_t)min(r1, n - 1) * 128 + 2 * t4;
    const __half* a2p = A + (size_t)min(r2, n - 1) * 128 + 2 * t4;

    float acc[16][4];
#pragma unroll
    for (int i = 0; i < 16; i++) {
        acc[i][0] = 0.f; acc[i][1] = 0.f; acc[i][2] = 0.f; acc[i][3] = 0.f;
    }

#pragma unroll
    for (int k0 = 0; k0 < 128; k0 += 16) {
        unsigned fa0 = *(const unsigned*)(a1p + k0);
        unsigned fa1 = *(const unsigned*)(a2p + k0);
        unsigned fa2 = *(const unsigned*)(a1p + k0 + 8);
        unsigned fa3 = *(const unsigned*)(a2p + k0 + 8);
        const __half* wb = ws + k0 + 2 * t4 + g * WS_STRIDE;
#pragma unroll
        for (int nt = 0; nt < 16; nt++) {
            unsigned b0 = *(const unsigned*)(wb + nt * 8 * WS_STRIDE);
            unsigned b1 = *(const unsigned*)(wb + nt * 8 * WS_STRIDE + 8);
            asm volatile(
                "mma.sync.aligned.m16n8k16.row.col.f32.f16.f16.f32 "
                "{%0,%1,%2,%3}, {%4,%5,%6,%7}, {%8,%9}, {%0,%1,%2,%3};"
                : "+f"(acc[nt][0]), "+f"(acc[nt][1]), "+f"(acc[nt][2]), "+f"(acc[nt][3])
                : "r"(fa0), "r"(fa1), "r"(fa2), "r"(fa3), "r"(b0), "r"(b1));
        }
    }

    bool ok1 = r1 < n, ok2 = r2 < n;
#pragma unroll
    for (int nt = 0; nt < 16; nt++) {
        int col = nt * 8 + 2 * t4;
        float2 bb = *(const float2*)&bias[col];
        if (ok1) {
            __half2 v = __floats2half2_rn(fmaxf(acc[nt][0] + bb.x, 0.f),
                                          fmaxf(acc[nt][1] + bb.y, 0.f));
            *(__half2*)&out[(size_t)r1 * 128 + col] = v;
        }
        if (ok2) {
            __half2 v = __floats2half2_rn(fmaxf(acc[nt][2] + bb.x, 0.f),
                                          fmaxf(acc[nt][3] + bb.y, 0.f));
            *(__half2*)&out[(size_t)r2 * 128 + col] = v;
        }
    }
}

// ---------------- graph pooling (graph_ids sorted): run-accumulate ----------
__global__ void k_pool(const int* __restrict__ gids, const __half* __restrict__ hfin, int n) {
    int d = threadIdx.x;
    int start = blockIdx.x * 128;
    if (start >= n) return;
    int end = min(start + 128, n);
    float acc = 0.f, c = 0.f;
    int g = gids[start];
    for (int i = start; i < end; i++) {
        int gi = gids[i];
        if (gi != g) {
            atomicAdd(&g_hg[g * D + d], acc);
            if (d == 0) atomicAdd(&g_cnt[g], c);
            acc = 0.f; c = 0.f; g = gi;
        }
        acc += __half2float(hfin[(size_t)i * D + d]);
        c += 1.f;
    }
    atomicAdd(&g_hg[g * D + d], acc);
    if (d == 0) atomicAdd(&g_cnt[g], c);
}

// ---------------- classifier head: (Wc1,bc1) twice (no act), then Wc2 -------
__global__ void k_cls(const float* __restrict__ Wc1, const float* __restrict__ bc1,
                      const float* __restrict__ Wc2, const float* __restrict__ bc2,
                      float* __restrict__ out) {
    __shared__ float x[128];
    __shared__ float t[128];
    __shared__ float red[128];
    int g = blockIdx.x, d = threadIdx.x;
    float c = fmaxf(g_cnt[g], 1.f);
    x[d] = g_hg[g * D + d] / c;
    __syncthreads();
    float a = bc1[d];
    for (int k = 0; k < 128; k++) a += Wc1[d * 128 + k] * x[k];
    t[d] = a;
    __syncthreads();
    float a2 = bc1[d];
    for (int k = 0; k < 128; k++) a2 += Wc1[d * 128 + k] * t[k];
    x[d] = a2;
    __syncthreads();
    red[d] = Wc2[d] * x[d];
    __syncthreads();
    for (int s = 64; s > 0; s >>= 1) {
        if (d < s) red[d] += red[d + s];
        __syncthreads();
    }
    if (d == 0) out[g] = red[0] + bc2[0];
}

// ---------------- launch (fork/join: feat conversion overlaps CSR build) ----
extern "C" void kernel_launch(void* const* d_in, const int* in_sizes, int n_in,
                              void* d_out, int out_size) {
    const float* feat = (const float*)d_in[0];
    const int*   src  = (const int*)d_in[1];
    const int*   dst  = (const int*)d_in[2];
    const int*   gids = (const int*)d_in[3];
    int base = (n_in == 15) ? 5 : 4;
    const float* W0  = (const float*)d_in[base + 0];
    const float* b0  = (const float*)d_in[base + 1];
    const float* W1  = (const float*)d_in[base + 2];
    const float* b1  = (const float*)d_in[base + 3];
    const float* W2  = (const float*)d_in[base + 4];
    const float* b2  = (const float*)d_in[base + 5];
    const float* Wc1 = (const float*)d_in[base + 6];
    const float* bc1 = (const float*)d_in[base + 7];
    const float* Wc2 = (const float*)d_in[base + 8];
    const float* bc2 = (const float*)d_in[base + 9];
    float* out = (float*)d_out;

    int nn = in_sizes[0] / (D - 1);
    int ne = in_sizes[1];
    int ng = out_size;

    // side stream + events for capture fork/join (host objects only; created
    // during the few real host calls, not during graph replays)
    cudaStream_t s2;
    cudaStreamCreateWithFlags(&s2, cudaStreamNonBlocking);
    cudaEvent_t evFork, evJoin;
    cudaEventCreateWithFlags(&evFork, cudaEventDisableTiming);
    cudaEventCreateWithFlags(&evJoin, cudaEventDisableTiming);

    // fork: side branch does feat/W conversion + hg/cnt zeroing
    cudaEventRecord(evFork, 0);
    cudaStreamWaitEvent(s2, evFork, 0);
    k_feat<<<(nn * D + 255) / 256, 256, 0, s2>>>(feat, W0, W1, W2, nn, ng);
    cudaEventRecord(evJoin, s2);

    // main branch: CSR build chain
    k_deg<<<(ne + 255) / 256, 256>>>(dst, ne);
    int nb = (nn + 1023) / 1024;
    k_scan1<<<nb, 1024>>>(nn);
    k_scan2b<<<nb, 1024>>>(nn, ne, nb);
    int fill_blocks = (ne + 2047) / 2048;
    int nth = fill_blocks * 256;
    k_fill<<<fill_blocks, 256>>>(src, dst, ne, nth);

    // join: layers need both CSR (main) and h feat cols (side)
    cudaStreamWaitEvent(0, evJoin, 0);

    __half *hA, *hB, *wh;
    cudaGetSymbolAddress((void**)&hA, g_h);
    cudaGetSymbolAddress((void**)&hB, g_agg);
    cudaGetSymbolAddress((void**)&wh, g_Wh);

    const size_t smem_gemm = 128 * WS_STRIDE * sizeof(__half);
    cudaFuncSetAttribute(k_gemm_hc, cudaFuncAttributeMaxDynamicSharedMemorySize, (int)smem_gemm);

    int agg_grid = (nn * 32 + 255) / 256;
    int gemm_grid = (nn + 127) / 128;

    const float* bs[3] = {b0, b1, b2};
    for (int l = 0; l < 3; l++) {
        k_agg<<<agg_grid, 256>>>(hA, hB, nn);
        k_gemm_hc<<<gemm_grid, 256, smem_gemm>>>(hB, wh + l * D * D, bs[l], hA, nn);
    }

    // pooling (final h in hA)
    k_pool<<<(nn + 127) / 128, 128>>>(gids, hA, nn);

    // classifier head
    k_cls<<<ng, 128>>>(Wc1, bc1, Wc2, bc2, out);

    // release host-side objects (safe: all work is enqueued/captured)
    cudaEventDestroy(evFork);
    cudaEventDestroy(evJoin);
    cudaStreamDestroy(s2);
}

// round 12
// speedup vs baseline: 1.0032x; 1.0032x over previous
#include <cuda_runtime.h>
#include <cuda_fp16.h>

#define NN_MAX 100000
#define NE_MAX 1600000
#define D 128
#define MAXG 4096
#define WS_STRIDE 136

// ---------------- scratch (static device globals; no allocs) ----------------
// g_degi / g_scomb start zero-initialized (module load); k_scan self-clears
// g_degi and k_degfeat clears g_scomb each launch, so replays stay correct.
__device__ __align__(16) __half g_h[NN_MAX * D];
__device__ __align__(16) __half g_agg[NN_MAX * D];
__device__ __align__(16) __half g_Wh[3 * D * D];
__device__ int   g_degi[NN_MAX];
__device__ int   g_off[NN_MAX + 1];
__device__ int   g_cur[NN_MAX];
__device__ int   g_esrc[NE_MAX];
__device__ float g_hg[MAXG * D];
__device__ float g_cnt[MAXG];
// decoupled-lookback state: one packed word per block.
// bits[63:32] = flag (0=invalid, 1=aggregate, 2=inclusive prefix),
// bits[31:0]  = value. Single 8-byte word => flag+value always consistent.
__device__ __align__(8) unsigned long long g_scomb[128];

// ------- fused prep: deg atomics + feat->fp16 + W conv + zero + scan reset --
__global__ void k_degfeat(const int* __restrict__ dst, const float* __restrict__ feat,
                          const float* __restrict__ W0, const float* __restrict__ W1,
                          const float* __restrict__ W2, int ne, int n, int ng) {
    int idx = blockIdx.x * blockDim.x + threadIdx.x;
    if (idx < ne) atomicAdd(&g_degi[dst[idx]], 1);
    if (idx < D * D) {
        g_Wh[idx] = __float2half(W0[idx]);
        g_Wh[D * D + idx] = __float2half(W1[idx]);
        g_Wh[2 * D * D + idx] = __float2half(W2[idx]);
    }
    if (idx < ng * D) g_hg[idx] = 0.f;
    if (idx < ng) g_cnt[idx] = 0.f;
    if (idx < 128) g_scomb[idx] = 0ull;  // reset lookback-scan state
    if (idx < n * D) {
        int d = idx & (D - 1);
        if (d != 0) {
            int node = idx >> 7;
            g_h[idx] = __float2half(feat[node * (D - 1) + d - 1]);
        }
    }
}

// -------- single-pass decoupled-lookback scan (packed flag|value word) ------
// Exclusive scan of g_degi -> g_off (+ primes g_cur, writes h[:,0]=deg,
// self-clears g_degi, writes g_off[n]=ne). 98 blocks <= 148 SMs => all
// blocks co-resident, predecessor spin cannot deadlock.
__global__ void k_scan(int n, int ne) {
    __shared__ int sh[1024];
    __shared__ int s_prefix;
    int b = blockIdx.x, t = threadIdx.x;
    int gid = b * 1024 + t;
    int v = (gid < n) ? g_degi[gid] : 0;
    if (gid < n) {
        g_h[(size_t)gid * D] = __float2half((float)v);
        g_degi[gid] = 0;  // re-zero for the next graph replay
    }
    sh[t] = v;
    __syncthreads();
    for (int s = 1; s < 1024; s <<= 1) {
        int u = (t >= s) ? sh[t - s] : 0;
        __syncthreads();
        sh[t] += u;
        __syncthreads();
    }
    int total = sh[1023];

    if (t == 0) {
        volatile unsigned long long* C = g_scomb;
        if (b == 0) {
            C[0] = (2ull << 32) | (unsigned)total;  // inclusive prefix ready
            s_prefix = 0;
        } else {
            C[b] = (1ull << 32) | (unsigned)total;  // aggregate ready
            int run = 0;
            int p = b - 1;
            while (true) {
                unsigned long long w;
                do { w = C[p]; } while ((w >> 32) == 0ull);
                int val = (int)(unsigned)(w & 0xffffffffull);
                run += val;
                if ((w >> 32) == 2ull) break;  // hit an inclusive prefix
                p--;
            }
            C[b] = (2ull << 32) | (unsigned)(run + total);
            s_prefix = run;
        }
    }
    __syncthreads();

    if (gid < n) {
        int o = sh[t] - v + s_prefix;  // exclusive scan value
        g_off[gid] = o;
        g_cur[gid] = o;
    }
    if (gid == 0) g_off[n] = ne;
}

// ---------------- CSR fill: 8 edges/thread, batched atomics (MLP=8) ---------
__global__ void k_fill(const int* __restrict__ src, const int* __restrict__ dst,
                       int ne, int nth) {
    int t = blockIdx.x * blockDim.x + threadIdx.x;
    int i[8], d[8], s[8], p[8];
#pragma unroll
    for (int j = 0; j < 8; j++) {
        i[j] = t + j * nth;
        d[j] = 0; s[j] = 0;
        if (i[j] < ne) { d[j] = dst[i[j]]; s[j] = src[i[j]]; }
    }
#pragma unroll
    for (int j = 0; j < 8; j++)
        if (i[j] < ne) p[j] = atomicAdd(&g_cur[d[j]], 1);
#pragma unroll
    for (int j = 0; j < 8; j++)
        if (i[j] < ne) g_esrc[p[j]] = s[j];
}

// ------- aggregation: warp/node, uint4 gather, predicated batched tail ------
__global__ void k_agg(const __half* __restrict__ hin, __half* __restrict__ aout, int n) {
    int warp = (blockIdx.x * blockDim.x + threadIdx.x) >> 5;
    int lane = threadIdx.x & 31;
    if (warp >= n) return;
    int hf = lane >> 4;     // 0 or 1 (which edge of the pair)
    int l16 = lane & 15;    // position within the row (8 halves each)
    int e0 = g_off[warp], e1 = g_off[warp + 1];
    const uint4* H = (const uint4*)hin;
    float acc[8];
#pragma unroll
    for (int i = 0; i < 8; i++) acc[i] = 0.f;

    int e = e0;
    for (; e + 7 < e1; e += 8) {
        int s[4];
#pragma unroll
        for (int j = 0; j < 4; j++) s[j] = g_esrc[e + 2 * j + hf];
        uint4 v[4];
#pragma unroll
        for (int j = 0; j < 4; j++) v[j] = H[(size_t)s[j] * 16 + l16];
#pragma unroll
        for (int j = 0; j < 4; j++) {
            float2 f;
            f = __half22float2(*(__half2*)&v[j].x); acc[0] += f.x; acc[1] += f.y;
            f = __half22float2(*(__half2*)&v[j].y); acc[2] += f.x; acc[3] += f.y;
            f = __half22float2(*(__half2*)&v[j].z); acc[4] += f.x; acc[5] += f.y;
            f = __half22float2(*(__half2*)&v[j].w); acc[6] += f.x; acc[7] += f.y;
        }
    }
    if (e < e1) {
        uint4 v[4];
#pragma unroll
        for (int j = 0; j < 4; j++) {
            int idx = e + 2 * j + hf;
            v[j] = make_uint4(0u, 0u, 0u, 0u);
            if (idx < e1) v[j] = H[(size_t)g_esrc[idx] * 16 + l16];
        }
#pragma unroll
        for (int j = 0; j < 4; j++) {
            float2 f;
            f = __half22float2(*(__half2*)&v[j].x); acc[0] += f.x; acc[1] += f.y;
            f = __half22float2(*(__half2*)&v[j].y); acc[2] += f.x; acc[3] += f.y;
            f = __half22float2(*(__half2*)&v[j].z); acc[4] += f.x; acc[5] += f.y;
            f = __half22float2(*(__half2*)&v[j].w); acc[6] += f.x; acc[7] += f.y;
        }
    }

#pragma unroll
    for (int i = 0; i < 8; i++) acc[i] += __shfl_xor_sync(0xffffffffu, acc[i], 16);

    int cnt = e1 - e0;
    if (lane < 16) {
        uint4 o;
        if (cnt > 0) {
            float inv = 1.0f / (float)cnt;
            __half2 h0 = __floats2half2_rn(acc[0] * inv, acc[1] * inv);
            __half2 h1 = __floats2half2_rn(acc[2] * inv, acc[3] * inv);
            __half2 h2 = __floats2half2_rn(acc[4] * inv, acc[5] * inv);
            __half2 h3 = __floats2half2_rn(acc[6] * inv, acc[7] * inv);
            o.x = *(unsigned*)&h0;
            o.y = *(unsigned*)&h1;
            o.z = *(unsigned*)&h2;
            o.w = *(unsigned*)&h3;
        } else {
            o = H[(size_t)warp * 16 + l16];  // zero in-degree keeps old h
        }
        ((uint4*)aout)[(size_t)warp * 16 + l16] = o;
    }
}

// ---------------- tensor-core GEMM (fp16 m16n8k16): out = relu(A @ W^T + b) --
__global__ __launch_bounds__(256, 2) void k_gemm_hc(const __half* __restrict__ A,
                                                    const __half* __restrict__ Wh,
                                                    const float* __restrict__ bias,
                                                    __half* __restrict__ out,
                                                    int n) {
    extern __shared__ __half ws[];  // [128][WS_STRIDE]
    int tid = threadIdx.x;

    const uint4* Wv = (const uint4*)Wh;
    for (int i = tid; i < 2048; i += 256) {
        int nrow = i >> 4;
        int kk = (i & 15) * 8;
        *(uint4*)&ws[nrow * WS_STRIDE + kk] = Wv[i];
    }
    __syncthreads();

    int warp = tid >> 5, lane = tid & 31;
    int g = lane >> 2;
    int t4 = lane & 3;
    int row0 = blockIdx.x * 128 + warp * 16;
    int r1 = row0 + g;
    int r2 = row0 + g + 8;
    const __half* a1p = A + (size_t)min(r1, n - 1) * 128 + 2 * t4;
    const __half* a2p = A + (size_t)min(r2, n - 1) * 128 + 2 * t4;

    float acc[16][4];
#pragma unroll
    for (int i = 0; i < 16; i++) {
        acc[i][0] = 0.f; acc[i][1] = 0.f; acc[i][2] = 0.f; acc[i][3] = 0.f;
    }

#pragma unroll
    for (int k0 = 0; k0 < 128; k0 += 16) {
        unsigned fa0 = *(const unsigned*)(a1p + k0);
        unsigned fa1 = *(const unsigned*)(a2p + k0);
        unsigned fa2 = *(const unsigned*)(a1p + k0 + 8);
        unsigned fa3 = *(const unsigned*)(a2p + k0 + 8);
        const __half* wb = ws + k0 + 2 * t4 + g * WS_STRIDE;
#pragma unroll
        for (int nt = 0; nt < 16; nt++) {
            unsigned b0 = *(const unsigned*)(wb + nt * 8 * WS_STRIDE);
            unsigned b1 = *(const unsigned*)(wb + nt * 8 * WS_STRIDE + 8);
            asm volatile(
                "mma.sync.aligned.m16n8k16.row.col.f32.f16.f16.f32 "
                "{%0,%1,%2,%3}, {%4,%5,%6,%7}, {%8,%9}, {%0,%1,%2,%3};"
                : "+f"(acc[nt][0]), "+f"(acc[nt][1]), "+f"(acc[nt][2]), "+f"(acc[nt][3])
                : "r"(fa0), "r"(fa1), "r"(fa2), "r"(fa3), "r"(b0), "r"(b1));
        }
    }

    bool ok1 = r1 < n, ok2 = r2 < n;
#pragma unroll
    for (int nt = 0; nt < 16; nt++) {
        int col = nt * 8 + 2 * t4;
        float2 bb = *(const float2*)&bias[col];
        if (ok1) {
            __half2 v = __floats2half2_rn(fmaxf(acc[nt][0] + bb.x, 0.f),
                                          fmaxf(acc[nt][1] + bb.y, 0.f));
            *(__half2*)&out[(size_t)r1 * 128 + col] = v;
        }
        if (ok2) {
            __half2 v = __floats2half2_rn(fmaxf(acc[nt][2] + bb.x, 0.f),
                                          fmaxf(acc[nt][3] + bb.y, 0.f));
            *(__half2*)&out[(size_t)r2 * 128 + col] = v;
        }
    }
}

// ---------------- graph pooling (graph_ids sorted): run-accumulate ----------
__global__ void k_pool(const int* __restrict__ gids, const __half* __restrict__ hfin, int n) {
    int d = threadIdx.x;
    int start = blockIdx.x * 128;
    if (start >= n) return;
    int end = min(start + 128, n);
    float acc = 0.f, c = 0.f;
    int g = gids[start];
    for (int i = start; i < end; i++) {
        int gi = gids[i];
        if (gi != g) {
            atomicAdd(&g_hg[g * D + d], acc);
            if (d == 0) atomicAdd(&g_cnt[g], c);
            acc = 0.f; c = 0.f; g = gi;
        }
        acc += __half2float(hfin[(size_t)i * D + d]);
        c += 1.f;
    }
    atomicAdd(&g_hg[g * D + d], acc);
    if (d == 0) atomicAdd(&g_cnt[g], c);
}

// ---------------- classifier head: (Wc1,bc1) twice (no act), then Wc2 -------
__global__ void k_cls(const float* __restrict__ Wc1, const float* __restrict__ bc1,
                      const float* __restrict__ Wc2, const float* __restrict__ bc2,
                      float* __restrict__ out) {
    __shared__ float x[128];
    __shared__ float t[128];
    __shared__ float red[128];
    int g = blockIdx.x, d = threadIdx.x;
    float c = fmaxf(g_cnt[g], 1.f);
    x[d] = g_hg[g * D + d] / c;
    __syncthreads();
    float a = bc1[d];
    for (int k = 0; k < 128; k++) a += Wc1[d * 128 + k] * x[k];
    t[d] = a;
    __syncthreads();
    float a2 = bc1[d];
    for (int k = 0; k < 128; k++) a2 += Wc1[d * 128 + k] * t[k];
    x[d] = a2;
    __syncthreads();
    red[d] = Wc2[d] * x[d];
    __syncthreads();
    for (int s = 64; s > 0; s >>= 1) {
        if (d < s) red[d] += red[d + s];
        __syncthreads();
    }
    if (d == 0) out[g] = red[0] + bc2[0];
}

// ---------------- launch ----------------
extern "C" void kernel_launch(void* const* d_in, const int* in_sizes, int n_in,
                              void* d_out, int out_size) {
    const float* feat = (const float*)d_in[0];
    const int*   src  = (const int*)d_in[1];
    const int*   dst  = (const int*)d_in[2];
    const int*   gids = (const int*)d_in[3];
    int base = (n_in == 15) ? 5 : 4;
    const float* W0  = (const float*)d_in[base + 0];
    const float* b0  = (const float*)d_in[base + 1];
    const float* W1  = (const float*)d_in[base + 2];
    const float* b1  = (const float*)d_in[base + 3];
    const float* W2  = (const float*)d_in[base + 4];
    const float* b2  = (const float*)d_in[base + 5];
    const float* Wc1 = (const float*)d_in[base + 6];
    const float* bc1 = (const float*)d_in[base + 7];
    const float* Wc2 = (const float*)d_in[base + 8];
    const float* bc2 = (const float*)d_in[base + 9];
    float* out = (float*)d_out;

    int nn = in_sizes[0] / (D - 1);
    int ne = in_sizes[1];
    int ng = out_size;

    // 1) fused prep: degrees + feat/W conversion + hg/cnt zero + scan reset
    k_degfeat<<<(nn * D + 255) / 256, 256>>>(dst, feat, W0, W1, W2, ne, nn, ng);

    // 2) single-pass decoupled-lookback scan -> CSR offsets (+h[:,0], g_cur)
    int nb = (nn + 1023) / 1024;
    k_scan<<<nb, 1024>>>(nn, ne);

    // 3) CSR fill: 8 edges per thread
    int fill_blocks = (ne + 2047) / 2048;
    int nth = fill_blocks * 256;
    k_fill<<<fill_blocks, 256>>>(src, dst, ne, nth);

    __half *hA, *hB, *wh;
    cudaGetSymbolAddress((void**)&hA, g_h);
    cudaGetSymbolAddress((void**)&hB, g_agg);
    cudaGetSymbolAddress((void**)&wh, g_Wh);

    const size_t smem_gemm = 128 * WS_STRIDE * sizeof(__half);
    cudaFuncSetAttribute(k_gemm_hc, cudaFuncAttributeMaxDynamicSharedMemorySize, (int)smem_gemm);

    int agg_grid = (nn * 32 + 255) / 256;
    int gemm_grid = (nn + 127) / 128;

    // 4..9) layers
    const float* bs[3] = {b0, b1, b2};
    for (int l = 0; l < 3; l++) {
        k_agg<<<agg_grid, 256>>>(hA, hB, nn);
        k_gemm_hc<<<gemm_grid, 256, smem_gemm>>>(hB, wh + l * D * D, bs[l], hA, nn);
    }

    // pooling (final h in hA)
    k_pool<<<(nn + 127) / 128, 128>>>(gids, hA, nn);

    // classifier head
    k_cls<<<ng, 128>>>(Wc1, bc1, Wc2, bc2, out);
}

// round 13
// speedup vs baseline: 1.0351x; 1.0318x over previous
#include <cuda_runtime.h>
#include <cuda_fp16.h>

#define NN_MAX 100000
#define NE_MAX 1600000
#define D 128
#define MAXG 4096
#define WS_STRIDE 136

// ---------------- scratch (static device globals; no allocs) ----------------
// g_degi / g_scomb start zero-initialized (module load); k_scan self-clears
// g_degi and k_degfeat clears g_scomb each launch, so replays stay correct.
__device__ __align__(16) __half g_h[NN_MAX * D];
__device__ __align__(16) __half g_agg[NN_MAX * D];
__device__ __align__(16) __half g_Wh[3 * D * D];
__device__ int   g_degi[NN_MAX];
__device__ int   g_off[NN_MAX + 1];
__device__ int   g_cur[NN_MAX];
__device__ int   g_esrc[NE_MAX];
__device__ float g_hg[MAXG * D];
__device__ float g_cnt[MAXG];
// decoupled-lookback state: one packed word per block.
// bits[63:32] = flag (0=invalid, 1=aggregate, 2=inclusive prefix),
// bits[31:0]  = value. Single 8-byte word => flag+value always consistent.
__device__ __align__(8) unsigned long long g_scomb[128];

// ------- fused prep: deg atomics + feat->fp16 + W conv + zero + scan reset --
__global__ void k_degfeat(const int* __restrict__ dst, const float* __restrict__ feat,
                          const float* __restrict__ W0, const float* __restrict__ W1,
                          const float* __restrict__ W2, int ne, int n, int ng) {
    int idx = blockIdx.x * blockDim.x + threadIdx.x;
    if (idx < ne) atomicAdd(&g_degi[dst[idx]], 1);
    if (idx < D * D) {
        g_Wh[idx] = __float2half(W0[idx]);
        g_Wh[D * D + idx] = __float2half(W1[idx]);
        g_Wh[2 * D * D + idx] = __float2half(W2[idx]);
    }
    if (idx < ng * D) g_hg[idx] = 0.f;
    if (idx < ng) g_cnt[idx] = 0.f;
    if (idx < 128) g_scomb[idx] = 0ull;  // reset lookback-scan state
    if (idx < n * D) {
        int d = idx & (D - 1);
        if (d != 0) {
            int node = idx >> 7;
            g_h[idx] = __float2half(feat[node * (D - 1) + d - 1]);
        }
    }
}

// -------- single-pass decoupled-lookback scan (packed flag|value word) ------
__global__ void k_scan(int n, int ne) {
    __shared__ int sh[1024];
    __shared__ int s_prefix;
    int b = blockIdx.x, t = threadIdx.x;
    int gid = b * 1024 + t;
    int v = (gid < n) ? g_degi[gid] : 0;
    if (gid < n) {
        g_h[(size_t)gid * D] = __float2half((float)v);
        g_degi[gid] = 0;  // re-zero for the next graph replay
    }
    sh[t] = v;
    __syncthreads();
    for (int s = 1; s < 1024; s <<= 1) {
        int u = (t >= s) ? sh[t - s] : 0;
        __syncthreads();
        sh[t] += u;
        __syncthreads();
    }
    int total = sh[1023];

    if (t == 0) {
        volatile unsigned long long* C = g_scomb;
        if (b == 0) {
            C[0] = (2ull << 32) | (unsigned)total;  // inclusive prefix ready
            s_prefix = 0;
        } else {
            C[b] = (1ull << 32) | (unsigned)total;  // aggregate ready
            int run = 0;
            int p = b - 1;
            while (true) {
                unsigned long long w;
                do { w = C[p]; } while ((w >> 32) == 0ull);
                int val = (int)(unsigned)(w & 0xffffffffull);
                run += val;
                if ((w >> 32) == 2ull) break;  // hit an inclusive prefix
                p--;
            }
            C[b] = (2ull << 32) | (unsigned)(run + total);
            s_prefix = run;
        }
    }
    __syncthreads();

    if (gid < n) {
        int o = sh[t] - v + s_prefix;  // exclusive scan value
        g_off[gid] = o;
        g_cur[gid] = o;
    }
    if (gid == 0) g_off[n] = ne;
}

// ---------------- CSR fill: 8 edges/thread, batched atomics (MLP=8) ---------
__global__ void k_fill(const int* __restrict__ src, const int* __restrict__ dst,
                       int ne, int nth) {
    int t = blockIdx.x * blockDim.x + threadIdx.x;
    int i[8], d[8], s[8], p[8];
#pragma unroll
    for (int j = 0; j < 8; j++) {
        i[j] = t + j * nth;
        d[j] = 0; s[j] = 0;
        if (i[j] < ne) { d[j] = dst[i[j]]; s[j] = src[i[j]]; }
    }
#pragma unroll
    for (int j = 0; j < 8; j++)
        if (i[j] < ne) p[j] = atomicAdd(&g_cur[d[j]], 1);
#pragma unroll
    for (int j = 0; j < 8; j++)
        if (i[j] < ne) g_esrc[p[j]] = s[j];
}

// ------- aggregation: warp/node, uint4 gather, fp16 pair-tree + fp32 flush --
// Issue-bound fix (R12 ncu: issue=73%, fma+alu=70%, L2 only 41%): sum each
// iteration's 4 edges with HADD2 (depth-2 tree, 12 instr) and flush once to
// fp32 (8 cvt + 8 add) instead of converting/adding every edge (~64 instr).
__device__ __forceinline__ __half2 u2h(unsigned u) { return *(__half2*)&u; }

__global__ void k_agg(const __half* __restrict__ hin, __half* __restrict__ aout, int n) {
    int warp = (blockIdx.x * blockDim.x + threadIdx.x) >> 5;
    int lane = threadIdx.x & 31;
    if (warp >= n) return;
    int hf = lane >> 4;     // 0 or 1 (which edge of the pair)
    int l16 = lane & 15;    // position within the row (8 halves each)
    int e0 = g_off[warp], e1 = g_off[warp + 1];
    const uint4* H = (const uint4*)hin;
    float acc[8];
#pragma unroll
    for (int i = 0; i < 8; i++) acc[i] = 0.f;

    int e = e0;
    for (; e + 7 < e1; e += 8) {
        int s[4];
#pragma unroll
        for (int j = 0; j < 4; j++) s[j] = g_esrc[e + 2 * j + hf];
        uint4 v[4];
#pragma unroll
        for (int j = 0; j < 4; j++) v[j] = H[(size_t)s[j] * 16 + l16];
        __half2 a0 = __hadd2(__hadd2(u2h(v[0].x), u2h(v[1].x)),
                             __hadd2(u2h(v[2].x), u2h(v[3].x)));
        __half2 a1 = __hadd2(__hadd2(u2h(v[0].y), u2h(v[1].y)),
                             __hadd2(u2h(v[2].y), u2h(v[3].y)));
        __half2 a2 = __hadd2(__hadd2(u2h(v[0].z), u2h(v[1].z)),
                             __hadd2(u2h(v[2].z), u2h(v[3].z)));
        __half2 a3 = __hadd2(__hadd2(u2h(v[0].w), u2h(v[1].w)),
                             __hadd2(u2h(v[2].w), u2h(v[3].w)));
        float2 f;
        f = __half22float2(a0); acc[0] += f.x; acc[1] += f.y;
        f = __half22float2(a1); acc[2] += f.x; acc[3] += f.y;
        f = __half22float2(a2); acc[4] += f.x; acc[5] += f.y;
        f = __half22float2(a3); acc[6] += f.x; acc[7] += f.y;
    }
    if (e < e1) {
        uint4 v[4];
#pragma unroll
        for (int j = 0; j < 4; j++) {
            int idx = e + 2 * j + hf;
            v[j] = make_uint4(0u, 0u, 0u, 0u);   // +0 is exact in fp16
            if (idx < e1) v[j] = H[(size_t)g_esrc[idx] * 16 + l16];
        }
        __half2 a0 = __hadd2(__hadd2(u2h(v[0].x), u2h(v[1].x)),
                             __hadd2(u2h(v[2].x), u2h(v[3].x)));
        __half2 a1 = __hadd2(__hadd2(u2h(v[0].y), u2h(v[1].y)),
                             __hadd2(u2h(v[2].y), u2h(v[3].y)));
        __half2 a2 = __hadd2(__hadd2(u2h(v[0].z), u2h(v[1].z)),
                             __hadd2(u2h(v[2].z), u2h(v[3].z)));
        __half2 a3 = __hadd2(__hadd2(u2h(v[0].w), u2h(v[1].w)),
                             __hadd2(u2h(v[2].w), u2h(v[3].w)));
        float2 f;
        f = __half22float2(a0); acc[0] += f.x; acc[1] += f.y;
        f = __half22float2(a1); acc[2] += f.x; acc[3] += f.y;
        f = __half22float2(a2); acc[4] += f.x; acc[5] += f.y;
        f = __half22float2(a3); acc[6] += f.x; acc[7] += f.y;
    }

#pragma unroll
    for (int i = 0; i < 8; i++) acc[i] += __shfl_xor_sync(0xffffffffu, acc[i], 16);

    int cnt = e1 - e0;
    if (lane < 16) {
        uint4 o;
        if (cnt > 0) {
            float inv = 1.0f / (float)cnt;
            __half2 h0 = __floats2half2_rn(acc[0] * inv, acc[1] * inv);
            __half2 h1 = __floats2half2_rn(acc[2] * inv, acc[3] * inv);
            __half2 h2 = __floats2half2_rn(acc[4] * inv, acc[5] * inv);
            __half2 h3 = __floats2half2_rn(acc[6] * inv, acc[7] * inv);
            o.x = *(unsigned*)&h0;
            o.y = *(unsigned*)&h1;
            o.z = *(unsigned*)&h2;
            o.w = *(unsigned*)&h3;
        } else {
            o = H[(size_t)warp * 16 + l16];  // zero in-degree keeps old h
        }
        ((uint4*)aout)[(size_t)warp * 16 + l16] = o;
    }
}

// ---------------- tensor-core GEMM (fp16 m16n8k16): out = relu(A @ W^T + b) --
__global__ __launch_bounds__(256, 2) void k_gemm_hc(const __half* __restrict__ A,
                                                    const __half* __restrict__ Wh,
                                                    const float* __restrict__ bias,
                                                    __half* __restrict__ out,
                                                    int n) {
    extern __shared__ __half ws[];  // [128][WS_STRIDE]
    int tid = threadIdx.x;

    const uint4* Wv = (const uint4*)Wh;
    for (int i = tid; i < 2048; i += 256) {
        int nrow = i >> 4;
        int kk = (i & 15) * 8;
        *(uint4*)&ws[nrow * WS_STRIDE + kk] = Wv[i];
    }
    __syncthreads();

    int warp = tid >> 5, lane = tid & 31;
    int g = lane >> 2;
    int t4 = lane & 3;
    int row0 = blockIdx.x * 128 + warp * 16;
    int r1 = row0 + g;
    int r2 = row0 + g + 8;
    const __half* a1p = A + (size_t)min(r1, n - 1) * 128 + 2 * t4;
    const __half* a2p = A + (size_t)min(r2, n - 1) * 128 + 2 * t4;

    float acc[16][4];
#pragma unroll
    for (int i = 0; i < 16; i++) {
        acc[i][0] = 0.f; acc[i][1] = 0.f; acc[i][2] = 0.f; acc[i][3] = 0.f;
    }

#pragma unroll
    for (int k0 = 0; k0 < 128; k0 += 16) {
        unsigned fa0 = *(const unsigned*)(a1p + k0);
        unsigned fa1 = *(const unsigned*)(a2p + k0);
        unsigned fa2 = *(const unsigned*)(a1p + k0 + 8);
        unsigned fa3 = *(const unsigned*)(a2p + k0 + 8);
        const __half* wb = ws + k0 + 2 * t4 + g * WS_STRIDE;
#pragma unroll
        for (int nt = 0; nt < 16; nt++) {
            unsigned b0 = *(const unsigned*)(wb + nt * 8 * WS_STRIDE);
            unsigned b1 = *(const unsigned*)(wb + nt * 8 * WS_STRIDE + 8);
            asm volatile(
                "mma.sync.aligned.m16n8k16.row.col.f32.f16.f16.f32 "
                "{%0,%1,%2,%3}, {%4,%5,%6,%7}, {%8,%9}, {%0,%1,%2,%3};"
                : "+f"(acc[nt][0]), "+f"(acc[nt][1]), "+f"(acc[nt][2]), "+f"(acc[nt][3])
                : "r"(fa0), "r"(fa1), "r"(fa2), "r"(fa3), "r"(b0), "r"(b1));
        }
    }

    bool ok1 = r1 < n, ok2 = r2 < n;
#pragma unroll
    for (int nt = 0; nt < 16; nt++) {
        int col = nt * 8 + 2 * t4;
        float2 bb = *(const float2*)&bias[col];
        if (ok1) {
            __half2 v = __floats2half2_rn(fmaxf(acc[nt][0] + bb.x, 0.f),
                                          fmaxf(acc[nt][1] + bb.y, 0.f));
            *(__half2*)&out[(size_t)r1 * 128 + col] = v;
        }
        if (ok2) {
            __half2 v = __floats2half2_rn(fmaxf(acc[nt][2] + bb.x, 0.f),
                                          fmaxf(acc[nt][3] + bb.y, 0.f));
            *(__half2*)&out[(size_t)r2 * 128 + col] = v;
        }
    }
}

// ---------------- graph pooling (graph_ids sorted): run-accumulate ----------
__global__ void k_pool(const int* __restrict__ gids, const __half* __restrict__ hfin, int n) {
    int d = threadIdx.x;
    int start = blockIdx.x * 128;
    if (start >= n) return;
    int end = min(start + 128, n);
    float acc = 0.f, c = 0.f;
    int g = gids[start];
    for (int i = start; i < end; i++) {
        int gi = gids[i];
        if (gi != g) {
            atomicAdd(&g_hg[g * D + d], acc);
            if (d == 0) atomicAdd(&g_cnt[g], c);
            acc = 0.f; c = 0.f; g = gi;
        }
        acc += __half2float(hfin[(size_t)i * D + d]);
        c += 1.f;
    }
    atomicAdd(&g_hg[g * D + d], acc);
    if (d == 0) atomicAdd(&g_cnt[g], c);
}

// ---------------- classifier head: (Wc1,bc1) twice (no act), then Wc2 -------
__global__ void k_cls(const float* __restrict__ Wc1, const float* __restrict__ bc1,
                      const float* __restrict__ Wc2, const float* __restrict__ bc2,
                      float* __restrict__ out) {
    __shared__ float x[128];
    __shared__ float t[128];
    __shared__ float red[128];
    int g = blockIdx.x, d = threadIdx.x;
    float c = fmaxf(g_cnt[g], 1.f);
    x[d] = g_hg[g * D + d] / c;
    __syncthreads();
    float a = bc1[d];
    for (int k = 0; k < 128; k++) a += Wc1[d * 128 + k] * x[k];
    t[d] = a;
    __syncthreads();
    float a2 = bc1[d];
    for (int k = 0; k < 128; k++) a2 += Wc1[d * 128 + k] * t[k];
    x[d] = a2;
    __syncthreads();
    red[d] = Wc2[d] * x[d];
    __syncthreads();
    for (int s = 64; s > 0; s >>= 1) {
        if (d < s) red[d] += red[d + s];
        __syncthreads();
    }
    if (d == 0) out[g] = red[0] + bc2[0];
}

// ---------------- launch ----------------
extern "C" void kernel_launch(void* const* d_in, const int* in_sizes, int n_in,
                              void* d_out, int out_size) {
    const float* feat = (const float*)d_in[0];
    const int*   src  = (const int*)d_in[1];
    const int*   dst  = (const int*)d_in[2];
    const int*   gids = (const int*)d_in[3];
    int base = (n_in == 15) ? 5 : 4;
    const float* W0  = (const float*)d_in[base + 0];
    const float* b0  = (const float*)d_in[base + 1];
    const float* W1  = (const float*)d_in[base + 2];
    const float* b1  = (const float*)d_in[base + 3];
    const float* W2  = (const float*)d_in[base + 4];
    const float* b2  = (const float*)d_in[base + 5];
    const float* Wc1 = (const float*)d_in[base + 6];
    const float* bc1 = (const float*)d_in[base + 7];
    const float* Wc2 = (const float*)d_in[base + 8];
    const float* bc2 = (const float*)d_in[base + 9];
    float* out = (float*)d_out;

    int nn = in_sizes[0] / (D - 1);
    int ne = in_sizes[1];
    int ng = out_size;

    // 1) fused prep: degrees + feat/W conversion + hg/cnt zero + scan reset
    k_degfeat<<<(nn * D + 255) / 256, 256>>>(dst, feat, W0, W1, W2, ne, nn, ng);

    // 2) single-pass decoupled-lookback scan -> CSR offsets (+h[:,0], g_cur)
    int nb = (nn + 1023) / 1024;
    k_scan<<<nb, 1024>>>(nn, ne);

    // 3) CSR fill: 8 edges per thread
    int fill_blocks = (ne + 2047) / 2048;
    int nth = fill_blocks * 256;
    k_fill<<<fill_blocks, 256>>>(src, dst, ne, nth);

    __half *hA, *hB, *wh;
    cudaGetSymbolAddress((void**)&hA, g_h);
    cudaGetSymbolAddress((void**)&hB, g_agg);
    cudaGetSymbolAddress((void**)&wh, g_Wh);

    const size_t smem_gemm = 128 * WS_STRIDE * sizeof(__half);
    cudaFuncSetAttribute(k_gemm_hc, cudaFuncAttributeMaxDynamicSharedMemorySize, (int)smem_gemm);

    int agg_grid = (nn * 32 + 255) / 256;
    int gemm_grid = (nn + 127) / 128;

    // 4..9) layers
    const float* bs[3] = {b0, b1, b2};
    for (int l = 0; l < 3; l++) {
        k_agg<<<agg_grid, 256>>>(hA, hB, nn);
        k_gemm_hc<<<gemm_grid, 256, smem_gemm>>>(hB, wh + l * D * D, bs[l], hA, nn);
    }

    // pooling (final h in hA)
    k_pool<<<(nn + 127) / 128, 128>>>(gids, hA, nn);

    // classifier head
    k_cls<<<ng, 128>>>(Wc1, bc1, Wc2, bc2, out);
}